// round 12
// baseline (speedup 1.0000x reference)
#include <cuda_runtime.h>

#define MT 64      // rows per block
#define HH 256     // hidden dim
#define RR 32      // rank
#define HSTR 260   // padded row stride for h in shared (16B aligned: 1040B)

// Packed, alpha-folded col weights: [blk][k4][rh][s] = float4 over k of col[k][2rh+s]*alpha
__device__ float4 g_cpkB[3][HH / 4][16][2];
// Transposed row weights: [blk][q][j] = float4(row[j][4q..4q+3])
__device__ float4 g_rwT[3][8][HH];

__device__ __forceinline__ float tanh_fast(float v) {
    float e = __expf(2.0f * v);
    return 1.0f - __fdividef(2.0f, e + 1.0f);
}

// packed dual-fp32 FMA (sm_103a FFMA2)
#define FMA2(acc, a, b) \
    asm("fma.rn.f32x2 %0, %1, %2, %0;" : "+l"(acc) : "l"(a), "l"(b))

__device__ __forceinline__ float hadd2(unsigned long long v) {
    float lo, hi;
    asm("mov.b64 {%0, %1}, %2;" : "=f"(lo), "=f"(hi) : "l"(v));
    return lo + hi;
}

__global__ void pack_kernel(const float* __restrict__ col0, const float* __restrict__ col1,
                            const float* __restrict__ col2, const float* __restrict__ row0,
                            const float* __restrict__ row1, const float* __restrict__ row2,
                            const float* __restrict__ al0, const float* __restrict__ al1,
                            const float* __restrict__ al2)
{
    int idx = blockIdx.x * blockDim.x + threadIdx.x;
    const int NC = 3 * (HH / 4) * 16 * 2;        // 6144 col-pack float4s
    if (idx < NC) {
        int b   = idx / ((HH / 4) * 32);
        int rem = idx % ((HH / 4) * 32);
        int k4  = rem / 32;
        int rh  = (rem % 32) >> 1;
        int s   = rem & 1;
        int r   = 2 * rh + s;
        const float* c = (b == 0) ? col0 : (b == 1) ? col1 : col2;
        const float* a = (b == 0) ? al0 : (b == 1) ? al1 : al2;
        const float av = a[r];
        g_cpkB[b][k4][rh][s] = make_float4(c[(4 * k4 + 0) * RR + r] * av,
                                           c[(4 * k4 + 1) * RR + r] * av,
                                           c[(4 * k4 + 2) * RR + r] * av,
                                           c[(4 * k4 + 3) * RR + r] * av);
        return;
    }
    idx -= NC;
    const int NR = 3 * 8 * HH;                   // 6144 row-pack float4s
    if (idx < NR) {
        int b = idx / (8 * HH);
        int q = (idx / HH) % 8;
        int j = idx % HH;
        const float* rw = (b == 0) ? row0 : (b == 1) ? row1 : row2;
        g_rwT[b][q][j] = make_float4(rw[j * RR + 4 * q + 0], rw[j * RR + 4 * q + 1],
                                     rw[j * RR + 4 * q + 2], rw[j * RR + 4 * q + 3]);
    }
}

extern __shared__ float smem[];

__global__ void __launch_bounds__(128, 3) pinn_kernel(
    const float* __restrict__ gx, const float* __restrict__ gt,
    const float* __restrict__ start_w, const float* __restrict__ start_b,
    const float* __restrict__ end_w, const float* __restrict__ end_b,
    float* __restrict__ out)
{
    float* h  = smem;                    // MT * HSTR
    float* u  = smem + MT * HSTR;        // MT * RR
    float* xs = u + MT * RR;             // MT
    float* ts = xs + MT;                 // MT

    const int tid  = threadIdx.x;        // 0..127
    const int base = blockIdx.x * MT;

    if (tid < MT) xs[tid] = gx[base + tid];
    else          ts[tid - MT] = gt[base + (tid - MT)];

    // ---- Phase A: h = tanh([x,t] @ start_w.T + start_b); thread owns j0=tid, j1=tid+128
    const int j0 = tid, j1 = tid + 128;
    const float w00 = start_w[2 * j0], w01 = start_w[2 * j0 + 1], b0 = start_b[j0];
    const float w10 = start_w[2 * j1], w11 = start_w[2 * j1 + 1], b1 = start_b[j1];
    __syncthreads();

    #pragma unroll 4
    for (int m = 0; m < MT; m++) {
        const float xm = xs[m], tm = ts[m];
        h[m * HSTR + j0] = tanh_fast(fmaf(xm, w00, fmaf(tm, w01, b0)));
        h[m * HSTR + j1] = tanh_fast(fmaf(xm, w10, fmaf(tm, w11, b1)));
    }
    __syncthreads();

    const int lane = tid & 31;
    const int wrp  = tid >> 5;           // 0..3
    const int g    = lane >> 4;          // row-group half within warp
    const int rh   = lane & 15;          // rank-pair index: r0=2rh, r1=2rh+1
    const int rowb = wrp * 16 + g * 8;   // this thread's 8-row base

    // Staggered row mapping: g=1 processes row (mm+1)&7 while g=0 processes mm.
    // Same-instruction addresses then differ by 9 (or 1) rows -> 16B bank offset
    // -> conflict-free broadcast LDS (vs 8 rows -> 0 mod 128 -> 2-way conflict).
    int rowidx[8];
    #pragma unroll
    for (int mm = 0; mm < 8; mm++) rowidx[mm] = rowb + ((mm + g) & 7);

    #pragma unroll
    for (int blk = 0; blk < 3; blk++) {
        // ---- Phase B: u[m][r] = sum_k h[m][k]*(col*alpha)[k][r]; 16 rows/warp, 2 r/lane
        const ulonglong2* cp = (const ulonglong2*)&g_cpkB[blk][0][0][0];
        unsigned long long accA[8], accB[8];
        #pragma unroll
        for (int mm = 0; mm < 8; mm++) { accA[mm] = 0ull; accB[mm] = 0ull; }

        #pragma unroll 2
        for (int k4 = 0; k4 < HH / 4; k4++) {
            const ulonglong2 cva = __ldg(&cp[(k4 * 16 + rh) * 2 + 0]);  // r0
            const ulonglong2 cvb = __ldg(&cp[(k4 * 16 + rh) * 2 + 1]);  // r1
            #pragma unroll
            for (int mm = 0; mm < 8; mm++) {
                const ulonglong2 hv =
                    *(const ulonglong2*)(h + rowidx[mm] * HSTR + 4 * k4);
                FMA2(accA[mm], hv.x, cva.x);
                FMA2(accA[mm], hv.y, cva.y);
                FMA2(accB[mm], hv.x, cvb.x);
                FMA2(accB[mm], hv.y, cvb.y);
            }
        }
        #pragma unroll
        for (int mm = 0; mm < 8; mm++) {
            *(float2*)(u + rowidx[mm] * RR + 2 * rh) =
                make_float2(hadd2(accA[mm]), hadd2(accB[mm]));
        }
        __syncthreads();

        // ---- Phase C: h[m][j] = tanh(sum_r u[m][r]*row[j][r]); 2 j/thread, 4 m/iter
        unsigned long long rp0[16], rp1[16];
        {
            const ulonglong2* rt = (const ulonglong2*)&g_rwT[blk][0][0];
            #pragma unroll
            for (int q = 0; q < 8; q++) {
                const ulonglong2 v0 = __ldg(&rt[q * HH + j0]);  // lane-consecutive
                const ulonglong2 v1 = __ldg(&rt[q * HH + j1]);
                rp0[2 * q] = v0.x; rp0[2 * q + 1] = v0.y;
                rp1[2 * q] = v1.x; rp1[2 * q + 1] = v1.y;
            }
        }
        for (int m = 0; m < MT; m += 4) {
            unsigned long long a00 = 0ull, a01 = 0ull, a10 = 0ull, a11 = 0ull;
            unsigned long long a20 = 0ull, a21 = 0ull, a30 = 0ull, a31 = 0ull;
            const ulonglong2* up0 = (const ulonglong2*)(u + m * RR);
            const ulonglong2* up1 = (const ulonglong2*)(u + (m + 1) * RR);
            const ulonglong2* up2 = (const ulonglong2*)(u + (m + 2) * RR);
            const ulonglong2* up3 = (const ulonglong2*)(u + (m + 3) * RR);
            #pragma unroll
            for (int q = 0; q < 8; q++) {
                const ulonglong2 v0 = up0[q];   // broadcast LDS.128, 1 wf
                const ulonglong2 v1 = up1[q];
                const ulonglong2 v2 = up2[q];
                const ulonglong2 v3 = up3[q];
                FMA2(a00, v0.x, rp0[2 * q]); FMA2(a00, v0.y, rp0[2 * q + 1]);
                FMA2(a01, v0.x, rp1[2 * q]); FMA2(a01, v0.y, rp1[2 * q + 1]);
                FMA2(a10, v1.x, rp0[2 * q]); FMA2(a10, v1.y, rp0[2 * q + 1]);
                FMA2(a11, v1.x, rp1[2 * q]); FMA2(a11, v1.y, rp1[2 * q + 1]);
                FMA2(a20, v2.x, rp0[2 * q]); FMA2(a20, v2.y, rp0[2 * q + 1]);
                FMA2(a21, v2.x, rp1[2 * q]); FMA2(a21, v2.y, rp1[2 * q + 1]);
                FMA2(a30, v3.x, rp0[2 * q]); FMA2(a30, v3.y, rp0[2 * q + 1]);
                FMA2(a31, v3.x, rp1[2 * q]); FMA2(a31, v3.y, rp1[2 * q + 1]);
            }
            h[m * HSTR + j0]       = tanh_fast(hadd2(a00));
            h[m * HSTR + j1]       = tanh_fast(hadd2(a01));
            h[(m + 1) * HSTR + j0] = tanh_fast(hadd2(a10));
            h[(m + 1) * HSTR + j1] = tanh_fast(hadd2(a11));
            h[(m + 2) * HSTR + j0] = tanh_fast(hadd2(a20));
            h[(m + 2) * HSTR + j1] = tanh_fast(hadd2(a21));
            h[(m + 3) * HSTR + j0] = tanh_fast(hadd2(a30));
            h[(m + 3) * HSTR + j1] = tanh_fast(hadd2(a31));
        }
        __syncthreads();
    }

    // ---- Phase D: out[m] = h[m].end_w + end_b; warp covers 16 rows x 2 halves
    const int m  = wrp * 16 + (lane & 15);
    const int hf = lane >> 4;
    float s = 0.0f;
    #pragma unroll
    for (int jo = 0; jo < 128; jo += 4) {
        const int jj = hf * 128 + jo;
        const float4 hv = *(const float4*)(h + m * HSTR + jj);
        const float4 wv = *(const float4*)(end_w + jj);
        s = fmaf(hv.x, wv.x, s);
        s = fmaf(hv.y, wv.y, s);
        s = fmaf(hv.z, wv.z, s);
        s = fmaf(hv.w, wv.w, s);
    }
    s += __shfl_xor_sync(0xffffffffu, s, 16);
    if (hf == 0) out[base + m] = s + end_b[0];
}

extern "C" void kernel_launch(void* const* d_in, const int* in_sizes, int n_in,
                              void* d_out, int out_size) {
    const float* x  = (const float*)d_in[0];
    const float* t  = (const float*)d_in[1];
    const float* sw = (const float*)d_in[2];
    const float* sb = (const float*)d_in[3];
    const float* ew = (const float*)d_in[4];
    const float* eb = (const float*)d_in[5];
    const float* c0 = (const float*)d_in[6];
    const float* c1 = (const float*)d_in[7];
    const float* c2 = (const float*)d_in[8];
    const float* r0 = (const float*)d_in[9];
    const float* r1 = (const float*)d_in[10];
    const float* r2 = (const float*)d_in[11];
    const float* a0 = (const float*)d_in[12];
    const float* a1 = (const float*)d_in[13];
    const float* a2 = (const float*)d_in[14];
    float* out = (float*)d_out;

    const int N = in_sizes[0];

    const int npack = 3 * (HH / 4) * 16 * 2 + 3 * 8 * HH;   // 12288
    pack_kernel<<<(npack + 255) / 256, 256>>>(c0, c1, c2, r0, r1, r2, a0, a1, a2);

    const int smem_bytes = (MT * HSTR + MT * RR + 2 * MT) * (int)sizeof(float);
    cudaFuncSetAttribute(pinn_kernel, cudaFuncAttributeMaxDynamicSharedMemorySize,
                         smem_bytes);
    pinn_kernel<<<N / MT, 128, smem_bytes>>>(x, t, sw, sb, ew, eb, out);
}

// round 14
// speedup vs baseline: 2.0751x; 2.0751x over previous
#include <cuda_runtime.h>
#include <cuda_bf16.h>
#include <cstdint>

// Fragment-order packed weights (uint2 per lane per tile), hi/lo bf16 splits.
// g_pb[blk][split][q(16)][j(4)][lane(32)][w(2)]  : colw*alpha, B-frag of D1 GEMM
// g_pc[blk][split][s(2)][n(32)][lane(32)][w(2)]  : roww,      B-frag of D2 GEMM
__device__ uint32_t g_pb[3][2][16][4][32][2];
__device__ uint32_t g_pc[3][2][2][32][32][2];

__device__ __forceinline__ float tanh_fast(float v) {
    float e = __expf(2.0f * v);
    return 1.0f - __fdividef(2.0f, e + 1.0f);
}

// d[0..3] += A(m16k16 bf16) * B(k16n8 bf16)   (f32 accumulate)
__device__ __forceinline__ void mma16816(float* d, const uint32_t* a, uint2 b) {
    asm volatile(
        "mma.sync.aligned.m16n8k16.row.col.f32.bf16.bf16.f32 "
        "{%0,%1,%2,%3}, {%4,%5,%6,%7}, {%8,%9}, {%0,%1,%2,%3};"
        : "+f"(d[0]), "+f"(d[1]), "+f"(d[2]), "+f"(d[3])
        : "r"(a[0]), "r"(a[1]), "r"(a[2]), "r"(a[3]), "r"(b.x), "r"(b.y));
}

// hi/lo bf16x2 split of (v0 -> low half, v1 -> high half)
__device__ __forceinline__ void split2(float v0, float v1, uint32_t& hi, uint32_t& lo) {
    uint32_t h;
    asm("cvt.rn.bf16x2.f32 %0, %1, %2;" : "=r"(h) : "f"(v1), "f"(v0));
    const float e0 = v0 - __uint_as_float(h << 16);
    const float e1 = v1 - __uint_as_float(h & 0xFFFF0000u);
    uint32_t l;
    asm("cvt.rn.bf16x2.f32 %0, %1, %2;" : "=r"(l) : "f"(e1), "f"(e0));
    hi = h; lo = l;
}

__device__ __forceinline__ uint32_t bf16x2_of(float v0, float v1, int split) {
    __nv_bfloat16 h0 = __float2bfloat16_rn(v0), h1 = __float2bfloat16_rn(v1);
    if (split) {
        h0 = __float2bfloat16_rn(v0 - __bfloat162float(h0));
        h1 = __float2bfloat16_rn(v1 - __bfloat162float(h1));
    }
    uint16_t b0 = __bfloat16_as_ushort(h0), b1 = __bfloat16_as_ushort(h1);
    return (uint32_t)b0 | ((uint32_t)b1 << 16);
}

__global__ void pack_kernel(const float* __restrict__ col0, const float* __restrict__ col1,
                            const float* __restrict__ col2, const float* __restrict__ row0,
                            const float* __restrict__ row1, const float* __restrict__ row2,
                            const float* __restrict__ al0, const float* __restrict__ al1,
                            const float* __restrict__ al2)
{
    int idx = blockIdx.x * blockDim.x + threadIdx.x;
    const int NPB = 3 * 2 * 16 * 4 * 32 * 2;   // 24576
    if (idx < NPB) {
        const int w = idx & 1, lane = (idx >> 1) & 31, j = (idx >> 6) & 3;
        const int q = (idx >> 8) & 15, split = (idx >> 12) & 1, b = idx >> 13;
        const int g = lane >> 2, t = lane & 3;
        const int k0 = 16 * q + 2 * t + 8 * w;
        const int n  = 8 * j + g;
        const float* c = (b == 0) ? col0 : (b == 1) ? col1 : col2;
        const float* a = (b == 0) ? al0 : (b == 1) ? al1 : al2;
        const float av = a[n];
        g_pb[b][split][q][j][lane][w] =
            bf16x2_of(c[k0 * 32 + n] * av, c[(k0 + 1) * 32 + n] * av, split);
        return;
    }
    idx -= NPB;
    if (idx < 3 * 2 * 2 * 32 * 32 * 2) {       // 24576
        const int w = idx & 1, lane = (idx >> 1) & 31, n = (idx >> 6) & 31;
        const int s = (idx >> 11) & 1, split = (idx >> 12) & 1, b = idx >> 13;
        const int g = lane >> 2, t = lane & 3;
        const int k0 = 16 * s + 2 * t + 8 * w;
        const int jj = 8 * n + g;
        const float* rw = (b == 0) ? row0 : (b == 1) ? row1 : row2;
        g_pc[b][split][s][n][lane][w] =
            bf16x2_of(rw[jj * 32 + k0], rw[jj * 32 + k0 + 1], split);
    }
}

__global__ void __launch_bounds__(128, 2) pinn_kernel(
    const float* __restrict__ gx, const float* __restrict__ gt,
    const float* __restrict__ start_w, const float* __restrict__ start_b,
    const float* __restrict__ end_w, const float* __restrict__ end_b,
    float* __restrict__ out)
{
    const int tid  = threadIdx.x;
    const int warp = tid >> 5;
    const int lane = tid & 31;
    const int g    = lane >> 2;     // row-in-tile group
    const int t    = lane & 3;      // col group
    const int r0   = blockIdx.x * 64 + warp * 16 + g;   // this thread's two rows
    const int r1   = r0 + 8;

    // ---- Phase A: h frags = tanh([x,t]@start_w.T + start_b), hi/lo bf16 ----
    uint32_t ahi[64], alo[64];
    {
        const float x0 = __ldg(gx + r0), x1 = __ldg(gx + r1);
        const float t0 = __ldg(gt + r0), t1 = __ldg(gt + r1);
        #pragma unroll
        for (int q = 0; q < 16; q++) {
            const int c0 = 16 * q + 2 * t;
            float h0[4], h1[4];   // (row r0 / r1) x cols {c0, c0+1, c0+8, c0+9}
            #pragma unroll
            for (int e = 0; e < 4; e++) {
                const int j  = c0 + (e >> 1) * 8 + (e & 1);
                const float w0 = __ldg(start_w + 2 * j);
                const float w1 = __ldg(start_w + 2 * j + 1);
                const float bb = __ldg(start_b + j);
                h0[e] = tanh_fast(fmaf(x0, w0, fmaf(t0, w1, bb)));
                h1[e] = tanh_fast(fmaf(x1, w0, fmaf(t1, w1, bb)));
            }
            split2(h0[0], h0[1], ahi[q * 4 + 0], alo[q * 4 + 0]);
            split2(h1[0], h1[1], ahi[q * 4 + 1], alo[q * 4 + 1]);
            split2(h0[2], h0[3], ahi[q * 4 + 2], alo[q * 4 + 2]);
            split2(h1[2], h1[3], ahi[q * 4 + 3], alo[q * 4 + 3]);
        }
    }

    float s0 = 0.0f, s1 = 0.0f;

    #pragma unroll 1
    for (int blk = 0; blk < 3; blk++) {
        const uint2* pbh = (const uint2*)&g_pb[blk][0][0][0][0][0];
        const uint2* pbl = (const uint2*)&g_pb[blk][1][0][0][0][0];
        const uint2* pch = (const uint2*)&g_pc[blk][0][0][0][0][0];
        const uint2* pcl = (const uint2*)&g_pc[blk][1][0][0][0][0];

        // ---- GEMM 1: D1[16,32] = h @ (col*alpha); 3 precision passes ----
        float d1[16];
        #pragma unroll
        for (int i = 0; i < 16; i++) d1[i] = 0.0f;
        #pragma unroll
        for (int q = 0; q < 16; q++) {
            #pragma unroll
            for (int j = 0; j < 4; j++) {
                const uint2 bh = __ldg(&pbh[(q * 4 + j) * 32 + lane]);
                const uint2 bl = __ldg(&pbl[(q * 4 + j) * 32 + lane]);
                mma16816(&d1[j * 4], &ahi[q * 4], bh);
                mma16816(&d1[j * 4], &alo[q * 4], bh);
                mma16816(&d1[j * 4], &ahi[q * 4], bl);
            }
        }

        // ---- u = D1 (linear), repack to A frags (m16k32) hi/lo ----
        uint32_t uhi[8], ulo[8];
        #pragma unroll
        for (int s = 0; s < 2; s++) {
            split2(d1[(2*s)*4 + 0], d1[(2*s)*4 + 1], uhi[s*4 + 0], ulo[s*4 + 0]);
            split2(d1[(2*s)*4 + 2], d1[(2*s)*4 + 3], uhi[s*4 + 1], ulo[s*4 + 1]);
            split2(d1[(2*s+1)*4 + 0], d1[(2*s+1)*4 + 1], uhi[s*4 + 2], ulo[s*4 + 2]);
            split2(d1[(2*s+1)*4 + 2], d1[(2*s+1)*4 + 3], uhi[s*4 + 3], ulo[s*4 + 3]);
        }

        // ---- GEMM 2: D2[16,256] = u @ row^T; 3 precision passes ----
        float d2[128];
        #pragma unroll
        for (int i = 0; i < 128; i++) d2[i] = 0.0f;
        #pragma unroll
        for (int n = 0; n < 32; n++) {
            #pragma unroll
            for (int s = 0; s < 2; s++) {
                const uint2 bh = __ldg(&pch[(s * 32 + n) * 32 + lane]);
                const uint2 bl = __ldg(&pcl[(s * 32 + n) * 32 + lane]);
                mma16816(&d2[n * 4], &uhi[s * 4], bh);
                mma16816(&d2[n * 4], &ulo[s * 4], bh);
                mma16816(&d2[n * 4], &uhi[s * 4], bl);
            }
        }

        if (blk < 2) {
            // ---- h' = tanh(D2): D-frags ARE next A-frags (in place) ----
            #pragma unroll
            for (int q = 0; q < 16; q++) {
                split2(tanh_fast(d2[(2*q)*4 + 0]), tanh_fast(d2[(2*q)*4 + 1]),
                       ahi[q*4 + 0], alo[q*4 + 0]);
                split2(tanh_fast(d2[(2*q)*4 + 2]), tanh_fast(d2[(2*q)*4 + 3]),
                       ahi[q*4 + 1], alo[q*4 + 1]);
                split2(tanh_fast(d2[(2*q+1)*4 + 0]), tanh_fast(d2[(2*q+1)*4 + 1]),
                       ahi[q*4 + 2], alo[q*4 + 2]);
                split2(tanh_fast(d2[(2*q+1)*4 + 2]), tanh_fast(d2[(2*q+1)*4 + 3]),
                       ahi[q*4 + 3], alo[q*4 + 3]);
            }
        } else {
            // ---- fused Phase D: dot with end_w ----
            #pragma unroll
            for (int n = 0; n < 32; n++) {
                const int c0 = 8 * n + 2 * t;
                const float e0 = __ldg(end_w + c0), e1 = __ldg(end_w + c0 + 1);
                s0 = fmaf(tanh_fast(d2[n*4 + 0]), e0, s0);
                s0 = fmaf(tanh_fast(d2[n*4 + 1]), e1, s0);
                s1 = fmaf(tanh_fast(d2[n*4 + 2]), e0, s1);
                s1 = fmaf(tanh_fast(d2[n*4 + 3]), e1, s1);
            }
        }
    }

    // reduce across the 4 lanes of each row group
    s0 += __shfl_xor_sync(0xffffffffu, s0, 1);
    s0 += __shfl_xor_sync(0xffffffffu, s0, 2);
    s1 += __shfl_xor_sync(0xffffffffu, s1, 1);
    s1 += __shfl_xor_sync(0xffffffffu, s1, 2);
    if (t == 0) {
        const float eb = __ldg(end_b);
        out[r0] = s0 + eb;
        out[r1] = s1 + eb;
    }
}

extern "C" void kernel_launch(void* const* d_in, const int* in_sizes, int n_in,
                              void* d_out, int out_size) {
    const float* x  = (const float*)d_in[0];
    const float* t  = (const float*)d_in[1];
    const float* sw = (const float*)d_in[2];
    const float* sb = (const float*)d_in[3];
    const float* ew = (const float*)d_in[4];
    const float* eb = (const float*)d_in[5];
    const float* c0 = (const float*)d_in[6];
    const float* c1 = (const float*)d_in[7];
    const float* c2 = (const float*)d_in[8];
    const float* r0 = (const float*)d_in[9];
    const float* r1 = (const float*)d_in[10];
    const float* r2 = (const float*)d_in[11];
    const float* a0 = (const float*)d_in[12];
    const float* a1 = (const float*)d_in[13];
    const float* a2 = (const float*)d_in[14];
    float* out = (float*)d_out;
    const int N = in_sizes[0];

    pack_kernel<<<(49152 + 255) / 256, 256>>>(c0, c1, c2, r0, r1, r2, a0, a1, a2);
    pinn_kernel<<<N / 64, 128>>>(x, t, sw, sb, ew, eb, out);
}